// round 15
// baseline (speedup 1.0000x reference)
#include <cuda_runtime.h>
#include <cstdint>

// path_generator_GAD  (N=131072 paths, T=251)
// s' = s + (b0+b1*s)*dt + (a0+a1*max(s,0))^g * Z*sqrt(dt)
//
// R15 = R13 (195us) with the fill path moved to cp.async.bulk (UBLKCP):
// one 80B bulk copy per (array,row) instead of five 16B LDGSTS. Completion
// via mbarrier expect_tx/complete_tx (full barrier count=1). Consumers
// unchanged except fence.proxy.async before the elected empty release
// (generic STS -> async-proxy bulk buffer reuse).

#define TSTEPS  251
#define DT_F    0.004f
#define SQRT_DT 0.063245553203367586f
#define S0_F    100.0f
#define TW      16
#define RW      20                  // floats per row slot (80B, 16B multiple)
#define CHUNKS  5                   // RW/4 float4 per row
#define NROWS   128
#define NTILES  16                  // ceil(250/16)
#define STAGES  3
#define PLANES  64                  // producer lanes (2 warps)
#define ARRF    (NROWS * RW)        // 2560 floats per array tile
#define BUFF    (6 * ARRF)          // 15360 floats per stage
#define DATA_OFF 64                 // floats reserved for barriers
#define TILE_BYTES      61440u      // 6*128*80
#define LAST_TILE_BYTES 39936u      // 6*(96*48 + 32*64)

__device__ __forceinline__ void bulk_cp(unsigned d, const float* src,
                                        unsigned bytes, unsigned mbar) {
    asm volatile(
        "cp.async.bulk.shared::cta.global.mbarrier::complete_tx::bytes "
        "[%0], [%1], %2, [%3];"
        :: "r"(d), "l"(src), "r"(bytes), "r"(mbar) : "memory");
}
__device__ __forceinline__ void mbar_init(unsigned a, unsigned cnt) {
    asm volatile("mbarrier.init.shared.b64 [%0], %1;" :: "r"(a), "r"(cnt));
}
__device__ __forceinline__ void mbar_arrive(unsigned a) {
    asm volatile("mbarrier.arrive.shared.b64 _, [%0];" :: "r"(a) : "memory");
}
__device__ __forceinline__ void mbar_expect_tx(unsigned a, unsigned bytes) {
    asm volatile("mbarrier.arrive.expect_tx.shared.b64 _, [%0], %1;"
                 :: "r"(a), "r"(bytes) : "memory");
}
__device__ __forceinline__ void fence_async_smem() {
    asm volatile("fence.proxy.async.shared::cta;" ::: "memory");
}
__device__ __forceinline__ unsigned elect_one() {
    unsigned pred;
    asm volatile(
        "{\n\t.reg .pred p;\n\t"
        "elect.sync _|p, 0xFFFFFFFF;\n\t"
        "selp.b32 %0, 1, 0, p;\n\t}" : "=r"(pred));
    return pred;
}
__device__ __forceinline__ void mbar_wait(unsigned a, unsigned ph) {
    unsigned done;
    asm volatile(
        "{\n\t.reg .pred p;\n\t"
        "mbarrier.try_wait.parity.acquire.cta.shared::cta.b64 p, [%1], %2;\n\t"
        "selp.b32 %0,1,0,p;\n\t}"
        : "=r"(done) : "r"(a), "r"(ph) : "memory");
    while (!done) {
        asm volatile(
            "{\n\t.reg .pred p;\n\t"
            "mbarrier.try_wait.parity.acquire.cta.shared::cta.b64 p, [%1], %2, 0x989680;\n\t"
            "selp.b32 %0,1,0,p;\n\t}"
            : "=r"(done) : "r"(a), "r"(ph) : "memory");
    }
}

template<int E>
__device__ __forceinline__ float elemf(const float4 (&v)[CHUNKS]) {
    constexpr int c = E >> 2;
    constexpr int m = E & 3;
    if constexpr (m == 0) return v[c].x;
    else if constexpr (m == 1) return v[c].y;
    else if constexpr (m == 2) return v[c].z;
    else return v[c].w;
}

template<int S>
__device__ __forceinline__ float run16(float s,
    const float4 (&vz)[CHUNKS], const float4 (&va0)[CHUNKS],
    const float4 (&va1)[CHUNKS], const float4 (&vb0)[CHUNKS],
    const float4 (&vb1)[CHUNKS], const float4 (&vg)[CHUNKS],
    float (&o)[TW])
{
#define ONE(J)                                                         \
    {                                                                  \
        float a0 = fmaf(elemf<S+J>(va0), 0.10f, 0.05f);                \
        float a1 = fmaf(elemf<S+J>(va1), 0.20f, 0.10f);                \
        float c0 = elemf<S+J>(vb0) * (0.05f * DT_F);                   \
        float m1 = fmaf(elemf<S+J>(vb1), 0.10f * DT_F, 1.0f);         \
        float g  = fmaf(elemf<S+J>(vg), 0.20f, 0.80f);                 \
        float zt = elemf<S+J>(vz) * SQRT_DT;                           \
        float base = fmaf(a1, fmaxf(s, 0.0f), a0);                     \
        float t = fmaf(__powf(base, g), zt, c0);                       \
        s = fmaf(s, m1, t);                                            \
        o[J] = s;                                                      \
    }
    ONE(0)  ONE(1)  ONE(2)  ONE(3)  ONE(4)  ONE(5)  ONE(6)  ONE(7)
    ONE(8)  ONE(9)  ONE(10) ONE(11) ONE(12) ONE(13) ONE(14) ONE(15)
#undef ONE
    return s;
}

__global__ void __launch_bounds__(192, 1)
gad_kernel(const float* __restrict__ Z,
           const float* __restrict__ Ua0,
           const float* __restrict__ Ua1,
           const float* __restrict__ Ub0,
           const float* __restrict__ Ub1,
           const float* __restrict__ Ug,
           float* __restrict__ out, int ngroups)
{
    extern __shared__ float smem[];
    const int tid = threadIdx.x;
    const unsigned sb = (unsigned)__cvta_generic_to_shared(smem);
    if (tid == 0) {
        #pragma unroll
        for (int s = 0; s < STAGES; ++s) {
            mbar_init(sb + s * 16,     1);   // full: 1 expect_tx arrive + tx
            mbar_init(sb + s * 16 + 8, 4);   // empty: 4 elected consumer lanes
        }
    }
    __syncthreads();

    float* data = smem + DATA_OFF;
    const unsigned dbase = sb + DATA_OFF * 4u;

    if (tid >= 128) {
        // ============ producer warps (2), persistent across groups ============
        const int lane = tid - 128;              // 0..63
        const float* const As[6] = { Z, Ua0, Ua1, Ub0, Ub1, Ug };
        int ps = 0, pph = 1;
        for (int g = blockIdx.x; g < ngroups; g += gridDim.x) {
            const int pB = g * NROWS;
            for (int k = 0; k < NTILES; ++k) {
                const unsigned ful = sb + ps * 16;
                const unsigned emp = ful + 8;
                mbar_wait(emp, pph);
                const unsigned stage = dbase + (unsigned)(ps * BUFF) * 4u;
                const int t0 = 1 + k * TW;
                if (k < NTILES - 1) {
                    if (tid == 128) mbar_expect_tx(ful, TILE_BYTES);
                    // 6 arrays x 128 rows / 64 lanes = 12 bulk copies/lane
                    #pragma unroll
                    for (int i = 0; i < 12; ++i) {
                        const int arr  = i >> 1;                 // compile-time
                        const int row  = ((i & 1) << 6) | lane;  // 0..127
                        const int slot = ((row & 3) << 5) | (row >> 2);
                        const int slack = (t0 - row) & 3;
                        const float* src = As[arr] + (pB + row) * TSTEPS + t0 - slack;
                        const unsigned d = stage +
                            (unsigned)((arr * ARRF + slot * RW) * 4);
                        bulk_cp(d, src, 80u, ful);
                    }
                } else {
                    // last tile (t0=241, w=10): per-row 48/64B windows sized so
                    // the global last row ends exactly at element 250.
                    if (tid == 128) mbar_expect_tx(ful, LAST_TILE_BYTES);
                    #pragma unroll
                    for (int i = 0; i < 12; ++i) {
                        const int arr  = i >> 1;
                        const int row  = ((i & 1) << 6) | lane;
                        const int slot = ((row & 3) << 5) | (row >> 2);
                        const int slack = (t0 - row) & 3;
                        const unsigned bytes = (slack == 3) ? 64u : 48u;
                        const float* src = As[arr] + (pB + row) * TSTEPS + t0 - slack;
                        const unsigned d = stage +
                            (unsigned)((arr * ARRF + slot * RW) * 4);
                        bulk_cp(d, src, bytes, ful);
                    }
                }
                if (++ps == STAGES) { ps = 0; pph ^= 1; }
            }
        }
    } else {
        // ============ consumer warps (4), persistent across groups ============
        const int w32  = tid >> 5;          // warp id 0..3
        const int lane = tid & 31;
        const int r    = 4 * lane + w32;    // my path row (slack-uniform warps)
        const int slot = tid;               // smem slot (80B lane stride)
        const int col  = lane & 15;         // writeback role: 16 cols
        const int rg   = lane >> 4;         // 0/1
        int cs = 0, cph = 0;

        for (int g = blockIdx.x; g < ngroups; g += gridDim.x) {
            const int pB = g * NROWS;
            out[(pB + r) * TSTEPS] = S0_F;  // column 0 = S0
            float s = S0_F;

            for (int k = 0; k < NTILES; ++k) {
                const unsigned ful = sb + cs * 16;
                const unsigned emp = ful + 8;
                mbar_wait(ful, cph);

                float* B = data + cs * BUFF;
                const int t0 = 1 + k * TW;
                const int s4 = (t0 - w32) & 3;      // warp-uniform slack

                if (k < NTILES - 1) {
                    float4 vz[CHUNKS], va0[CHUNKS], va1[CHUNKS],
                           vb0[CHUNKS], vb1[CHUNKS], vg[CHUNKS];
                    const float4* p = reinterpret_cast<const float4*>(B) + slot * CHUNKS;
                    const int A4 = ARRF / 4;        // 640 float4 per array
                    #pragma unroll
                    for (int c = 0; c < CHUNKS; ++c) {
                        vz[c]  = p[0 * A4 + c];
                        va0[c] = p[1 * A4 + c];
                        va1[c] = p[2 * A4 + c];
                        vb0[c] = p[3 * A4 + c];
                        vb1[c] = p[4 * A4 + c];
                        vg[c]  = p[5 * A4 + c];
                    }
                    float o[TW];
                    switch (s4) {   // warp-uniform: exactly one case executes
                        case 0: s = run16<0>(s, vz, va0, va1, vb0, vb1, vg, o); break;
                        case 1: s = run16<1>(s, vz, va0, va1, vb0, vb1, vg, o); break;
                        case 2: s = run16<2>(s, vz, va0, va1, vb0, vb1, vg, o); break;
                        default: s = run16<3>(s, vz, va0, va1, vb0, vb1, vg, o); break;
                    }
                    float4* q = reinterpret_cast<float4*>(B) + slot * CHUNKS;
                    q[0] = make_float4(o[0],  o[1],  o[2],  o[3]);
                    q[1] = make_float4(o[4],  o[5],  o[6],  o[7]);
                    q[2] = make_float4(o[8],  o[9],  o[10], o[11]);
                    q[3] = make_float4(o[12], o[13], o[14], o[15]);

                    __syncwarp();
                    // warp-local transposed writeback (wv == 16 always here)
                    #pragma unroll
                    for (int ii = 0; ii < 16; ++ii) {
                        const int li  = rg * 16 + ii;         // 0..31
                        const int row = 4 * li + w32;
                        out[(pB + row) * TSTEPS + t0 + col] =
                            B[(w32 * 32 + li) * RW + col];
                    }
                    __syncwarp();
                } else {
                    // last tile (w=10): scalar path
                    const int wv = TSTEPS - t0;               // 10
                    for (int j = 0; j < wv; ++j) {
                        const int si = slot * RW + s4 + j;
                        float a0 = fmaf(B[1 * ARRF + si], 0.10f, 0.05f);
                        float a1 = fmaf(B[2 * ARRF + si], 0.20f, 0.10f);
                        float c0 = B[3 * ARRF + si] * (0.05f * DT_F);
                        float m1 = fmaf(B[4 * ARRF + si], 0.10f * DT_F, 1.0f);
                        float gg = fmaf(B[5 * ARRF + si], 0.20f, 0.80f);
                        float zt = B[si] * SQRT_DT;
                        float base = fmaf(a1, fmaxf(s, 0.0f), a0);
                        float t = fmaf(__powf(base, gg), zt, c0);
                        s = fmaf(s, m1, t);
                        B[slot * RW + j] = s;
                    }
                    __syncwarp();
                    if (col < wv) {
                        #pragma unroll
                        for (int ii = 0; ii < 16; ++ii) {
                            const int li  = rg * 16 + ii;
                            const int row = 4 * li + w32;
                            out[(pB + row) * TSTEPS + t0 + col] =
                                B[(w32 * 32 + li) * RW + col];
                        }
                    }
                    __syncwarp();
                }
                if (elect_one()) {
                    fence_async_smem();   // generic STS -> async-proxy reuse
                    mbar_arrive(emp);     // one arrive per warp
                }
                if (++cs == STAGES) { cs = 0; cph ^= 1; }
            }
        }
    }
}

extern "C" void kernel_launch(void* const* d_in, const int* in_sizes, int n_in,
                              void* d_out, int out_size)
{
    const float* Z   = (const float*)d_in[0];
    const float* Ua0 = (const float*)d_in[1];
    const float* Ua1 = (const float*)d_in[2];
    const float* Ub0 = (const float*)d_in[3];
    const float* Ub1 = (const float*)d_in[4];
    const float* Ug  = (const float*)d_in[5];
    float* out = (float*)d_out;

    const int N = in_sizes[0] / TSTEPS;             // 131072
    const int ngroups = (N + NROWS - 1) / NROWS;    // 1024
    const int blocks = ngroups < 148 ? ngroups : 148;

    const size_t smem = (size_t)(DATA_OFF + STAGES * BUFF) * sizeof(float); // 184576 B
    cudaFuncSetAttribute(gad_kernel, cudaFuncAttributeMaxDynamicSharedMemorySize, (int)smem);

    gad_kernel<<<blocks, 192, smem>>>(Z, Ua0, Ua1, Ub0, Ub1, Ug, out, ngroups);
}

// round 16
// speedup vs baseline: 6.5397x; 6.5397x over previous
#include <cuda_runtime.h>
#include <cstdint>

// path_generator_GAD  (N=131072 paths, T=251)
// s' = s + (b0+b1*s)*dt + (a0+a1*max(s,0))^g * Z*sqrt(dt)
//
// R16 = R13 restructured for TWO blocks/SM: TW=12, RW=16 (64B windows),
// 2 stages -> 98.6KB smem/block -> 2 resident pipelines per SM that fill
// each other's stage-turnaround bubbles. Grid 512, exactly 2 groups/block.
// Keeps: dual producers, warp-uniform slack, elect arrives, short chain.

#define TSTEPS  251
#define DT_F    0.004f
#define SQRT_DT 0.063245553203367586f
#define S0_F    100.0f
#define TW      12
#define RW      16                  // floats per row slot (64B)
#define CHUNKS  4                   // RW/4 float4 per row
#define NROWS   128
#define NTILES  21                  // 20 full (12) + last (10)
#define STAGES  2
#define PLANES  64                  // producer lanes (2 warps)
#define ARRF    (NROWS * RW)        // 2048 floats per array tile
#define BUFF    (6 * ARRF)          // 12288 floats per stage
#define DATA_OFF 64                 // floats reserved for barriers

__device__ __forceinline__ void cp16(unsigned sa, const float* g) {
    asm volatile("cp.async.cg.shared.global [%0], [%1], 16;" :: "r"(sa), "l"(g));
}
__device__ __forceinline__ void cp4(unsigned sa, const float* g) {
    asm volatile("cp.async.ca.shared.global [%0], [%1], 4;" :: "r"(sa), "l"(g));
}
__device__ __forceinline__ void mbar_init(unsigned a, unsigned cnt) {
    asm volatile("mbarrier.init.shared.b64 [%0], %1;" :: "r"(a), "r"(cnt));
}
__device__ __forceinline__ void mbar_arrive(unsigned a) {
    asm volatile("mbarrier.arrive.shared.b64 _, [%0];" :: "r"(a) : "memory");
}
__device__ __forceinline__ void cp_arrive_noinc(unsigned a) {
    asm volatile("cp.async.mbarrier.arrive.noinc.shared.b64 [%0];" :: "r"(a) : "memory");
}
__device__ __forceinline__ unsigned elect_one() {
    unsigned pred;
    asm volatile(
        "{\n\t.reg .pred p;\n\t"
        "elect.sync _|p, 0xFFFFFFFF;\n\t"
        "selp.b32 %0, 1, 0, p;\n\t}" : "=r"(pred));
    return pred;
}
__device__ __forceinline__ void mbar_wait(unsigned a, unsigned ph) {
    unsigned done;
    asm volatile(
        "{\n\t.reg .pred p;\n\t"
        "mbarrier.try_wait.parity.acquire.cta.shared::cta.b64 p, [%1], %2;\n\t"
        "selp.b32 %0,1,0,p;\n\t}"
        : "=r"(done) : "r"(a), "r"(ph) : "memory");
    while (!done) {
        asm volatile(
            "{\n\t.reg .pred p;\n\t"
            "mbarrier.try_wait.parity.acquire.cta.shared::cta.b64 p, [%1], %2, 0x989680;\n\t"
            "selp.b32 %0,1,0,p;\n\t}"
            : "=r"(done) : "r"(a), "r"(ph) : "memory");
    }
}

template<int E>
__device__ __forceinline__ float elemf(const float4 (&v)[CHUNKS]) {
    constexpr int c = E >> 2;
    constexpr int m = E & 3;
    if constexpr (m == 0) return v[c].x;
    else if constexpr (m == 1) return v[c].y;
    else if constexpr (m == 2) return v[c].z;
    else return v[c].w;
}

template<int S>
__device__ __forceinline__ float run12(float s,
    const float4 (&vz)[CHUNKS], const float4 (&va0)[CHUNKS],
    const float4 (&va1)[CHUNKS], const float4 (&vb0)[CHUNKS],
    const float4 (&vb1)[CHUNKS], const float4 (&vg)[CHUNKS],
    float (&o)[TW])
{
#define ONE(J)                                                         \
    {                                                                  \
        float a0 = fmaf(elemf<S+J>(va0), 0.10f, 0.05f);                \
        float a1 = fmaf(elemf<S+J>(va1), 0.20f, 0.10f);                \
        float c0 = elemf<S+J>(vb0) * (0.05f * DT_F);                   \
        float m1 = fmaf(elemf<S+J>(vb1), 0.10f * DT_F, 1.0f);         \
        float g  = fmaf(elemf<S+J>(vg), 0.20f, 0.80f);                 \
        float zt = elemf<S+J>(vz) * SQRT_DT;                           \
        float base = fmaf(a1, fmaxf(s, 0.0f), a0);                     \
        float t = fmaf(__powf(base, g), zt, c0);                       \
        s = fmaf(s, m1, t);                                            \
        o[J] = s;                                                      \
    }
    ONE(0)  ONE(1)  ONE(2)  ONE(3)  ONE(4)  ONE(5)
    ONE(6)  ONE(7)  ONE(8)  ONE(9)  ONE(10) ONE(11)
#undef ONE
    return s;
}

__global__ void __launch_bounds__(192, 2)
gad_kernel(const float* __restrict__ Z,
           const float* __restrict__ Ua0,
           const float* __restrict__ Ua1,
           const float* __restrict__ Ub0,
           const float* __restrict__ Ub1,
           const float* __restrict__ Ug,
           float* __restrict__ out, int ngroups)
{
    extern __shared__ float smem[];
    const int tid = threadIdx.x;
    const unsigned sb = (unsigned)__cvta_generic_to_shared(smem);
    if (tid == 0) {
        #pragma unroll
        for (int s = 0; s < STAGES; ++s) {
            mbar_init(sb + s * 16,     PLANES);  // full: 64 producer lanes
            mbar_init(sb + s * 16 + 8, 4);       // empty: 4 elected consumer lanes
        }
    }
    __syncthreads();

    float* data = smem + DATA_OFF;
    const unsigned dbase = sb + DATA_OFF * 4u;
    const int g0 = blockIdx.x * 2;               // 2 groups per block
    const int g1 = min(g0 + 2, ngroups);

    if (tid >= 128) {
        // ============ producer warps (2) ============
        const int lane = tid - 128;              // 0..63
        int ps = 0, pph = 1;
        for (int g = g0; g < g1; ++g) {
            const int pB = g * NROWS;
            for (int k = 0; k < NTILES; ++k) {
                const unsigned ful = sb + ps * 16;
                const unsigned emp = ful + 8;
                mbar_wait(emp, pph);
                const unsigned stage = dbase + (unsigned)(ps * BUFF) * 4u;
                const int t0 = 1 + k * TW;
                if (k < NTILES - 1) {
                    // 128 rows x 4 chunks x 6 arrays / 64 lanes = 48 cp16/lane
                    #pragma unroll
                    for (int i = 0; i < 8; ++i) {
                        const int c    = lane + PLANES * i;  // 0..511
                        const int row  = c >> 2;
                        const int kk   = c & 3;              // 0..3
                        const int slot = ((row & 3) << 5) | (row >> 2);
                        const int slack = (t0 - row) & 3;
                        const int gi = (pB + row) * TSTEPS + t0 - slack + kk * 4;
                        const unsigned d = stage + (unsigned)(slot * RW + kk * 4) * 4u;
                        cp16(d + 0u * (ARRF * 4), Z   + gi);
                        cp16(d + 1u * (ARRF * 4), Ua0 + gi);
                        cp16(d + 2u * (ARRF * 4), Ua1 + gi);
                        cp16(d + 3u * (ARRF * 4), Ub0 + gi);
                        cp16(d + 4u * (ARRF * 4), Ub1 + gi);
                        cp16(d + 5u * (ARRF * 4), Ug  + gi);
                    }
                } else {
                    // last tile (t0=241, w=10): exact 4B copies
                    const int w = TSTEPS - t0;               // 10
                    for (int idx = lane; idx < NROWS * w; idx += PLANES) {
                        const int row  = idx / w;
                        const int j    = idx - row * w;
                        const int slot = ((row & 3) << 5) | (row >> 2);
                        const int slack = (t0 - row) & 3;
                        const int gi = (pB + row) * TSTEPS + t0 + j;
                        const unsigned d = stage + (unsigned)(slot * RW + slack + j) * 4u;
                        cp4(d + 0u * (ARRF * 4), Z   + gi);
                        cp4(d + 1u * (ARRF * 4), Ua0 + gi);
                        cp4(d + 2u * (ARRF * 4), Ua1 + gi);
                        cp4(d + 3u * (ARRF * 4), Ub0 + gi);
                        cp4(d + 4u * (ARRF * 4), Ub1 + gi);
                        cp4(d + 5u * (ARRF * 4), Ug  + gi);
                    }
                }
                cp_arrive_noinc(ful);
                if (++ps == STAGES) { ps = 0; pph ^= 1; }
            }
        }
    } else {
        // ============ consumer warps (4) ============
        const int w32  = tid >> 5;          // warp id 0..3
        const int lane = tid & 31;
        const int r    = 4 * lane + w32;    // my path row (slack-uniform warps)
        const int slot = tid;               // smem slot (64B lane stride)
        const int col  = lane & 15;         // writeback role
        const int rg   = lane >> 4;         // 0/1
        int cs = 0, cph = 0;

        for (int g = g0; g < g1; ++g) {
            const int pB = g * NROWS;
            out[(pB + r) * TSTEPS] = S0_F;  // column 0 = S0
            float s = S0_F;

            for (int k = 0; k < NTILES; ++k) {
                const unsigned ful = sb + cs * 16;
                const unsigned emp = ful + 8;
                mbar_wait(ful, cph);

                float* B = data + cs * BUFF;
                const int t0 = 1 + k * TW;
                const int s4 = (t0 - w32) & 3;      // warp-uniform slack

                if (k < NTILES - 1) {
                    float4 vz[CHUNKS], va0[CHUNKS], va1[CHUNKS],
                           vb0[CHUNKS], vb1[CHUNKS], vg[CHUNKS];
                    const float4* p = reinterpret_cast<const float4*>(B) + slot * CHUNKS;
                    const int A4 = ARRF / 4;        // 512 float4 per array
                    #pragma unroll
                    for (int c = 0; c < CHUNKS; ++c) {
                        vz[c]  = p[0 * A4 + c];
                        va0[c] = p[1 * A4 + c];
                        va1[c] = p[2 * A4 + c];
                        vb0[c] = p[3 * A4 + c];
                        vb1[c] = p[4 * A4 + c];
                        vg[c]  = p[5 * A4 + c];
                    }
                    float o[TW];
                    switch (s4) {   // warp-uniform: exactly one case executes
                        case 0: s = run12<0>(s, vz, va0, va1, vb0, vb1, vg, o); break;
                        case 1: s = run12<1>(s, vz, va0, va1, vb0, vb1, vg, o); break;
                        case 2: s = run12<2>(s, vz, va0, va1, vb0, vb1, vg, o); break;
                        default: s = run12<3>(s, vz, va0, va1, vb0, vb1, vg, o); break;
                    }
                    // stage outputs back into consumed Z slot (12 floats)
                    float* q = B + slot * RW;
                    q[0]  = o[0];  q[1]  = o[1];  q[2]  = o[2];  q[3]  = o[3];
                    q[4]  = o[4];  q[5]  = o[5];  q[6]  = o[6];  q[7]  = o[7];
                    q[8]  = o[8];  q[9]  = o[9];  q[10] = o[10]; q[11] = o[11];

                    __syncwarp();
                    // warp-local transposed writeback (12 cols)
                    if (col < TW) {
                        #pragma unroll
                        for (int ii = 0; ii < 16; ++ii) {
                            const int li  = rg * 16 + ii;     // 0..31
                            const int row = 4 * li + w32;
                            out[(pB + row) * TSTEPS + t0 + col] =
                                B[(w32 * 32 + li) * RW + col];
                        }
                    }
                    __syncwarp();
                } else {
                    // last tile (w=10): scalar path
                    const int wv = TSTEPS - t0;               // 10
                    for (int j = 0; j < wv; ++j) {
                        const int si = slot * RW + s4 + j;
                        float a0 = fmaf(B[1 * ARRF + si], 0.10f, 0.05f);
                        float a1 = fmaf(B[2 * ARRF + si], 0.20f, 0.10f);
                        float c0 = B[3 * ARRF + si] * (0.05f * DT_F);
                        float m1 = fmaf(B[4 * ARRF + si], 0.10f * DT_F, 1.0f);
                        float gg = fmaf(B[5 * ARRF + si], 0.20f, 0.80f);
                        float zt = B[si] * SQRT_DT;
                        float base = fmaf(a1, fmaxf(s, 0.0f), a0);
                        float t = fmaf(__powf(base, gg), zt, c0);
                        s = fmaf(s, m1, t);
                        B[slot * RW + j] = s;
                    }
                    __syncwarp();
                    if (col < wv) {
                        #pragma unroll
                        for (int ii = 0; ii < 16; ++ii) {
                            const int li  = rg * 16 + ii;
                            const int row = 4 * li + w32;
                            out[(pB + row) * TSTEPS + t0 + col] =
                                B[(w32 * 32 + li) * RW + col];
                        }
                    }
                    __syncwarp();
                }
                if (elect_one()) mbar_arrive(emp);   // one arrive per warp
                if (++cs == STAGES) { cs = 0; cph ^= 1; }
            }
        }
    }
}

extern "C" void kernel_launch(void* const* d_in, const int* in_sizes, int n_in,
                              void* d_out, int out_size)
{
    const float* Z   = (const float*)d_in[0];
    const float* Ua0 = (const float*)d_in[1];
    const float* Ua1 = (const float*)d_in[2];
    const float* Ub0 = (const float*)d_in[3];
    const float* Ub1 = (const float*)d_in[4];
    const float* Ug  = (const float*)d_in[5];
    float* out = (float*)d_out;

    const int N = in_sizes[0] / TSTEPS;             // 131072
    const int ngroups = (N + NROWS - 1) / NROWS;    // 1024
    const int blocks = (ngroups + 1) / 2;           // 512, 2 groups each

    const size_t smem = (size_t)(DATA_OFF + STAGES * BUFF) * sizeof(float); // 98560 B
    cudaFuncSetAttribute(gad_kernel, cudaFuncAttributeMaxDynamicSharedMemorySize, (int)smem);

    gad_kernel<<<blocks, 192, smem>>>(Z, Ua0, Ua1, Ub0, Ub1, Ug, out, ngroups);
}

// round 17
// speedup vs baseline: 6.7508x; 1.0323x over previous
#include <cuda_runtime.h>
#include <cstdint>

// path_generator_GAD  (N=131072 paths, T=251)
// s' = s + (b0+b1*s)*dt + (a0+a1*max(s,0))^g * Z*sqrt(dt)
//
// R17 = R13 structure with a DEEPER, FINER ring: TW=12 / RW=16 (64B
// windows) x 4 stages (192.3KB smem). Producer runs up to 3 tiles ahead,
// halving boundary exposure per byte. 2-stage rings are proven poison
// (R10, R16); 3-stage R13 = 195us is the baseline to beat.

#define TSTEPS  251
#define DT_F    0.004f
#define SQRT_DT 0.063245553203367586f
#define S0_F    100.0f
#define TW      12
#define RW      16                  // floats per row slot (64B)
#define CHUNKS  4                   // RW/4 float4 per row
#define NROWS   128
#define NTILES  21                  // 20 full (12 steps) + last (10)
#define STAGES  4
#define PLANES  64                  // producer lanes (2 warps)
#define ARRF    (NROWS * RW)        // 2048 floats per array tile
#define BUFF    (6 * ARRF)          // 12288 floats per stage
#define DATA_OFF 64                 // floats reserved for barriers

__device__ __forceinline__ void cp16(unsigned sa, const float* g) {
    asm volatile("cp.async.cg.shared.global [%0], [%1], 16;" :: "r"(sa), "l"(g));
}
__device__ __forceinline__ void cp4(unsigned sa, const float* g) {
    asm volatile("cp.async.ca.shared.global [%0], [%1], 4;" :: "r"(sa), "l"(g));
}
__device__ __forceinline__ void mbar_init(unsigned a, unsigned cnt) {
    asm volatile("mbarrier.init.shared.b64 [%0], %1;" :: "r"(a), "r"(cnt));
}
__device__ __forceinline__ void mbar_arrive(unsigned a) {
    asm volatile("mbarrier.arrive.shared.b64 _, [%0];" :: "r"(a) : "memory");
}
__device__ __forceinline__ void cp_arrive_noinc(unsigned a) {
    asm volatile("cp.async.mbarrier.arrive.noinc.shared.b64 [%0];" :: "r"(a) : "memory");
}
__device__ __forceinline__ unsigned elect_one() {
    unsigned pred;
    asm volatile(
        "{\n\t.reg .pred p;\n\t"
        "elect.sync _|p, 0xFFFFFFFF;\n\t"
        "selp.b32 %0, 1, 0, p;\n\t}" : "=r"(pred));
    return pred;
}
__device__ __forceinline__ void mbar_wait(unsigned a, unsigned ph) {
    unsigned done;
    asm volatile(
        "{\n\t.reg .pred p;\n\t"
        "mbarrier.try_wait.parity.acquire.cta.shared::cta.b64 p, [%1], %2;\n\t"
        "selp.b32 %0,1,0,p;\n\t}"
        : "=r"(done) : "r"(a), "r"(ph) : "memory");
    while (!done) {
        asm volatile(
            "{\n\t.reg .pred p;\n\t"
            "mbarrier.try_wait.parity.acquire.cta.shared::cta.b64 p, [%1], %2, 0x989680;\n\t"
            "selp.b32 %0,1,0,p;\n\t}"
            : "=r"(done) : "r"(a), "r"(ph) : "memory");
    }
}

template<int E>
__device__ __forceinline__ float elemf(const float4 (&v)[CHUNKS]) {
    constexpr int c = E >> 2;
    constexpr int m = E & 3;
    if constexpr (m == 0) return v[c].x;
    else if constexpr (m == 1) return v[c].y;
    else if constexpr (m == 2) return v[c].z;
    else return v[c].w;
}

template<int S>
__device__ __forceinline__ float run12(float s,
    const float4 (&vz)[CHUNKS], const float4 (&va0)[CHUNKS],
    const float4 (&va1)[CHUNKS], const float4 (&vb0)[CHUNKS],
    const float4 (&vb1)[CHUNKS], const float4 (&vg)[CHUNKS],
    float (&o)[TW])
{
#define ONE(J)                                                         \
    {                                                                  \
        float a0 = fmaf(elemf<S+J>(va0), 0.10f, 0.05f);                \
        float a1 = fmaf(elemf<S+J>(va1), 0.20f, 0.10f);                \
        float c0 = elemf<S+J>(vb0) * (0.05f * DT_F);                   \
        float m1 = fmaf(elemf<S+J>(vb1), 0.10f * DT_F, 1.0f);         \
        float g  = fmaf(elemf<S+J>(vg), 0.20f, 0.80f);                 \
        float zt = elemf<S+J>(vz) * SQRT_DT;                           \
        float base = fmaf(a1, fmaxf(s, 0.0f), a0);                     \
        float t = fmaf(__powf(base, g), zt, c0);                       \
        s = fmaf(s, m1, t);                                            \
        o[J] = s;                                                      \
    }
    ONE(0)  ONE(1)  ONE(2)  ONE(3)  ONE(4)  ONE(5)
    ONE(6)  ONE(7)  ONE(8)  ONE(9)  ONE(10) ONE(11)
#undef ONE
    return s;
}

__global__ void __launch_bounds__(192, 1)
gad_kernel(const float* __restrict__ Z,
           const float* __restrict__ Ua0,
           const float* __restrict__ Ua1,
           const float* __restrict__ Ub0,
           const float* __restrict__ Ub1,
           const float* __restrict__ Ug,
           float* __restrict__ out, int ngroups)
{
    extern __shared__ float smem[];
    const int tid = threadIdx.x;
    const unsigned sb = (unsigned)__cvta_generic_to_shared(smem);
    if (tid == 0) {
        #pragma unroll
        for (int s = 0; s < STAGES; ++s) {
            mbar_init(sb + s * 16,     PLANES);  // full: 64 producer lanes
            mbar_init(sb + s * 16 + 8, 4);       // empty: 4 elected consumer lanes
        }
    }
    __syncthreads();

    float* data = smem + DATA_OFF;
    const unsigned dbase = sb + DATA_OFF * 4u;

    if (tid >= 128) {
        // ============ producer warps (2), persistent across groups ============
        const int lane = tid - 128;              // 0..63
        int ps = 0, pph = 1;
        for (int g = blockIdx.x; g < ngroups; g += gridDim.x) {
            const int pB = g * NROWS;
            for (int k = 0; k < NTILES; ++k) {
                const unsigned ful = sb + ps * 16;
                const unsigned emp = ful + 8;
                mbar_wait(emp, pph);
                const unsigned stage = dbase + (unsigned)(ps * BUFF) * 4u;
                const int t0 = 1 + k * TW;
                if (k < NTILES - 1) {
                    // 128 rows x 4 chunks x 6 arrays / 64 lanes = 48 cp16/lane
                    #pragma unroll
                    for (int i = 0; i < 8; ++i) {
                        const int c    = lane + PLANES * i;  // 0..511
                        const int row  = c >> 2;
                        const int kk   = c & 3;              // 0..3
                        const int slot = ((row & 3) << 5) | (row >> 2);
                        const int slack = (t0 - row) & 3;
                        const int gi = (pB + row) * TSTEPS + t0 - slack + kk * 4;
                        const unsigned d = stage + (unsigned)(slot * RW + kk * 4) * 4u;
                        cp16(d + 0u * (ARRF * 4), Z   + gi);
                        cp16(d + 1u * (ARRF * 4), Ua0 + gi);
                        cp16(d + 2u * (ARRF * 4), Ua1 + gi);
                        cp16(d + 3u * (ARRF * 4), Ub0 + gi);
                        cp16(d + 4u * (ARRF * 4), Ub1 + gi);
                        cp16(d + 5u * (ARRF * 4), Ug  + gi);
                    }
                } else {
                    // last tile (t0=241, w=10): exact 4B copies
                    const int w = TSTEPS - t0;               // 10
                    for (int idx = lane; idx < NROWS * w; idx += PLANES) {
                        const int row  = idx / w;
                        const int j    = idx - row * w;
                        const int slot = ((row & 3) << 5) | (row >> 2);
                        const int slack = (t0 - row) & 3;
                        const int gi = (pB + row) * TSTEPS + t0 + j;
                        const unsigned d = stage + (unsigned)(slot * RW + slack + j) * 4u;
                        cp4(d + 0u * (ARRF * 4), Z   + gi);
                        cp4(d + 1u * (ARRF * 4), Ua0 + gi);
                        cp4(d + 2u * (ARRF * 4), Ua1 + gi);
                        cp4(d + 3u * (ARRF * 4), Ub0 + gi);
                        cp4(d + 4u * (ARRF * 4), Ub1 + gi);
                        cp4(d + 5u * (ARRF * 4), Ug  + gi);
                    }
                }
                cp_arrive_noinc(ful);
                if (++ps == STAGES) { ps = 0; pph ^= 1; }
            }
        }
    } else {
        // ============ consumer warps (4), persistent across groups ============
        const int w32  = tid >> 5;          // warp id 0..3
        const int lane = tid & 31;
        const int r    = 4 * lane + w32;    // my path row (slack-uniform warps)
        const int slot = tid;               // smem slot (64B lane stride)
        const int col  = lane & 15;         // writeback role
        const int rg   = lane >> 4;         // 0/1
        int cs = 0, cph = 0;

        for (int g = blockIdx.x; g < ngroups; g += gridDim.x) {
            const int pB = g * NROWS;
            out[(pB + r) * TSTEPS] = S0_F;  // column 0 = S0
            float s = S0_F;

            for (int k = 0; k < NTILES; ++k) {
                const unsigned ful = sb + cs * 16;
                const unsigned emp = ful + 8;
                mbar_wait(ful, cph);

                float* B = data + cs * BUFF;
                const int t0 = 1 + k * TW;
                const int s4 = (t0 - w32) & 3;      // warp-uniform slack

                if (k < NTILES - 1) {
                    float4 vz[CHUNKS], va0[CHUNKS], va1[CHUNKS],
                           vb0[CHUNKS], vb1[CHUNKS], vg[CHUNKS];
                    const float4* p = reinterpret_cast<const float4*>(B) + slot * CHUNKS;
                    const int A4 = ARRF / 4;        // 512 float4 per array
                    #pragma unroll
                    for (int c = 0; c < CHUNKS; ++c) {
                        vz[c]  = p[0 * A4 + c];
                        va0[c] = p[1 * A4 + c];
                        va1[c] = p[2 * A4 + c];
                        vb0[c] = p[3 * A4 + c];
                        vb1[c] = p[4 * A4 + c];
                        vg[c]  = p[5 * A4 + c];
                    }
                    float o[TW];
                    switch (s4) {   // warp-uniform: exactly one case executes
                        case 0: s = run12<0>(s, vz, va0, va1, vb0, vb1, vg, o); break;
                        case 1: s = run12<1>(s, vz, va0, va1, vb0, vb1, vg, o); break;
                        case 2: s = run12<2>(s, vz, va0, va1, vb0, vb1, vg, o); break;
                        default: s = run12<3>(s, vz, va0, va1, vb0, vb1, vg, o); break;
                    }
                    // stage outputs back into consumed Z slot (12 floats)
                    float* q = B + slot * RW;
                    q[0]  = o[0];  q[1]  = o[1];  q[2]  = o[2];  q[3]  = o[3];
                    q[4]  = o[4];  q[5]  = o[5];  q[6]  = o[6];  q[7]  = o[7];
                    q[8]  = o[8];  q[9]  = o[9];  q[10] = o[10]; q[11] = o[11];

                    __syncwarp();
                    // warp-local transposed writeback (12 cols)
                    if (col < TW) {
                        #pragma unroll
                        for (int ii = 0; ii < 16; ++ii) {
                            const int li  = rg * 16 + ii;     // 0..31
                            const int row = 4 * li + w32;
                            out[(pB + row) * TSTEPS + t0 + col] =
                                B[(w32 * 32 + li) * RW + col];
                        }
                    }
                    __syncwarp();
                } else {
                    // last tile (w=10): scalar path
                    const int wv = TSTEPS - t0;               // 10
                    for (int j = 0; j < wv; ++j) {
                        const int si = slot * RW + s4 + j;
                        float a0 = fmaf(B[1 * ARRF + si], 0.10f, 0.05f);
                        float a1 = fmaf(B[2 * ARRF + si], 0.20f, 0.10f);
                        float c0 = B[3 * ARRF + si] * (0.05f * DT_F);
                        float m1 = fmaf(B[4 * ARRF + si], 0.10f * DT_F, 1.0f);
                        float gg = fmaf(B[5 * ARRF + si], 0.20f, 0.80f);
                        float zt = B[si] * SQRT_DT;
                        float base = fmaf(a1, fmaxf(s, 0.0f), a0);
                        float t = fmaf(__powf(base, gg), zt, c0);
                        s = fmaf(s, m1, t);
                        B[slot * RW + j] = s;
                    }
                    __syncwarp();
                    if (col < wv) {
                        #pragma unroll
                        for (int ii = 0; ii < 16; ++ii) {
                            const int li  = rg * 16 + ii;
                            const int row = 4 * li + w32;
                            out[(pB + row) * TSTEPS + t0 + col] =
                                B[(w32 * 32 + li) * RW + col];
                        }
                    }
                    __syncwarp();
                }
                if (elect_one()) mbar_arrive(emp);   // one arrive per warp
                if (++cs == STAGES) { cs = 0; cph ^= 1; }
            }
        }
    }
}

extern "C" void kernel_launch(void* const* d_in, const int* in_sizes, int n_in,
                              void* d_out, int out_size)
{
    const float* Z   = (const float*)d_in[0];
    const float* Ua0 = (const float*)d_in[1];
    const float* Ua1 = (const float*)d_in[2];
    const float* Ub0 = (const float*)d_in[3];
    const float* Ub1 = (const float*)d_in[4];
    const float* Ug  = (const float*)d_in[5];
    float* out = (float*)d_out;

    const int N = in_sizes[0] / TSTEPS;             // 131072
    const int ngroups = (N + NROWS - 1) / NROWS;    // 1024
    const int blocks = ngroups < 148 ? ngroups : 148;

    const size_t smem = (size_t)(DATA_OFF + STAGES * BUFF) * sizeof(float); // 196864 B
    cudaFuncSetAttribute(gad_kernel, cudaFuncAttributeMaxDynamicSharedMemorySize, (int)smem);

    gad_kernel<<<blocks, 192, smem>>>(Z, Ua0, Ua1, Ub0, Ub1, Ug, out, ngroups);
}